// round 1
// baseline (speedup 1.0000x reference)
#include <cuda_runtime.h>
#include <cstdint>

// VQ-VAE codebook quantization, fused fp32 GEMM + argmin + gather + loss.
// N=262144 rows (x), K=1024 codes, D=64.
// Output layout (fp32): [0,N): Z (as float), [N, N+N*D): q_with_st, then vq_loss, commitment_loss.

#define DDIM 64
#define BM 128       // rows per block
#define BK 128       // codes per chunk
#define NTHREADS 256

__device__ double g_loss_accum;
__device__ float  g_csq[4096];

// ---------------------------------------------------------------------------
// c_sq[k] = sum_d codebook[k][d]^2
__global__ void csq_kernel(const float* __restrict__ cb, int K) {
    int k = blockIdx.x * blockDim.x + threadIdx.x;
    if (k < K) {
        float s = 0.f;
        #pragma unroll
        for (int d = 0; d < DDIM; d++) {
            float v = cb[(size_t)k * DDIM + d];
            s += v * v;
        }
        g_csq[k] = s;
    }
}

__global__ void zero_kernel() { g_loss_accum = 0.0; }

__global__ void finalize_kernel(float* __restrict__ out, int N) {
    double mean = g_loss_accum / ((double)N * (double)DDIM);
    size_t base = (size_t)N + (size_t)N * DDIM;
    out[base]     = (float)mean;  // vq_loss
    out[base + 1] = (float)mean;  // commitment_loss (numerically identical)
}

// ---------------------------------------------------------------------------
// fma.rn.f32x2 packed fp32 FMA (Blackwell): two fp32 FMAs per instruction.
__device__ __forceinline__ unsigned long long fma2(unsigned long long a,
                                                   unsigned long long b,
                                                   unsigned long long c) {
    unsigned long long d;
    asm("fma.rn.f32x2 %0, %1, %2, %3;" : "=l"(d) : "l"(a), "l"(b), "l"(c));
    return d;
}

// Dynamic smem layout (floats):
//   As  : [64][128]  x tile transposed (d-major)        8192 floats
//   Bs2 : [64][256]  code tile, each value DUPLICATED   16384 floats
//   xsq : [128]
//   csq : [128]
// Aliased into Bs2 after mainloop:
//   redval [128][16] float, redidx [128][16] int, zsh [128] int, dred [256] double
#define SMEM_FLOATS (64*128 + 64*256 + 128 + 128)

__global__ __launch_bounds__(NTHREADS, 2)
void vq_main_kernel(const float* __restrict__ x, const float* __restrict__ cb,
                    float* __restrict__ out, int N, int K) {
    extern __shared__ float smem[];
    float* As  = smem;                 // 64*128
    float* Bs2 = smem + 64 * 128;      // 64*256
    float* xsq = Bs2 + 64 * 256;       // 128
    float* csq = xsq + 128;            // 128

    // aliases (valid only after mainloop)
    float* redval = Bs2;                       // 128*16 floats
    int*   redidx = (int*)(Bs2 + 128 * 16);    // 128*16 ints
    int*   zsh    = (int*)(Bs2 + 128 * 32);    // 128 ints
    double* dred  = (double*)(Bs2 + 4352);     // 256 doubles (8B aligned)

    const int tid = threadIdx.x;
    const int tx  = tid & 15;   // code group 0..15
    const int ty  = tid >> 4;   // row group 0..15
    const int rowBase = blockIdx.x * BM;

    // ---- load x tile transposed: As[d][row] ----
    #pragma unroll
    for (int t = 0; t < 8; t++) {
        int lin = tid + t * NTHREADS;          // 0..2047
        int row = lin >> 4;
        int dg  = (lin & 15) << 2;
        float4 v = *(const float4*)(x + (size_t)(rowBase + row) * DDIM + dg);
        As[(dg + 0) * 128 + row] = v.x;
        As[(dg + 1) * 128 + row] = v.y;
        As[(dg + 2) * 128 + row] = v.z;
        As[(dg + 3) * 128 + row] = v.w;
    }
    __syncthreads();

    // ---- x_sq per row (sequential over d, matching reference formula class) ----
    if (tid < 128) {
        float s = 0.f;
        #pragma unroll
        for (int d = 0; d < DDIM; d++) {
            float v = As[d * 128 + tid];
            s += v * v;
        }
        xsq[tid] = s;
    }

    // running argmin per thread: 8 rows
    float rv[8];
    int   ri[8];
    #pragma unroll
    for (int i = 0; i < 8; i++) { rv[i] = 3.4e38f; ri[i] = 0; }

    #pragma unroll 1
    for (int cbase = 0; cbase < K; cbase += BK) {
        __syncthreads();   // previous chunk compute done before overwriting Bs2

        // ---- load code chunk, transposed + duplicated: Bs2[d][2k]=Bs2[d][2k+1]=c[k][d]
        #pragma unroll
        for (int t = 0; t < 8; t++) {
            int lin  = tid + t * NTHREADS;
            int code = lin >> 4;
            int dg   = (lin & 15) << 2;
            float4 v = *(const float4*)(cb + (size_t)(cbase + code) * DDIM + dg);
            *(float2*)&Bs2[(dg + 0) * 256 + 2 * code] = make_float2(v.x, v.x);
            *(float2*)&Bs2[(dg + 1) * 256 + 2 * code] = make_float2(v.y, v.y);
            *(float2*)&Bs2[(dg + 2) * 256 + 2 * code] = make_float2(v.z, v.z);
            *(float2*)&Bs2[(dg + 3) * 256 + 2 * code] = make_float2(v.w, v.w);
        }
        if (tid < 128) csq[tid] = g_csq[cbase + tid];
        __syncthreads();

        // ---- mainloop: acc[p][j] = dot(rows (2p,2p+1), code tx*8+j) as f32x2 pairs
        unsigned long long acc[4][8];
        #pragma unroll
        for (int p = 0; p < 4; p++)
            #pragma unroll
            for (int j = 0; j < 8; j++) acc[p][j] = 0ULL;

        #pragma unroll 16
        for (int d = 0; d < DDIM; d++) {
            const unsigned long long* arow =
                (const unsigned long long*)&As[d * 128 + ty * 8];   // 4 row-pairs
            const unsigned long long* brow =
                (const unsigned long long*)&Bs2[d * 256 + tx * 16]; // 8 splats
            unsigned long long ap[4], bp[8];
            #pragma unroll
            for (int p = 0; p < 4; p++) ap[p] = arow[p];
            #pragma unroll
            for (int j = 0; j < 8; j++) bp[j] = brow[j];
            #pragma unroll
            for (int p = 0; p < 4; p++)
                #pragma unroll
                for (int j = 0; j < 8; j++)
                    acc[p][j] = fma2(ap[p], bp[j], acc[p][j]);
        }

        // ---- distances + argmin update (ascending code index, strict <) ----
        float xq[8];
        #pragma unroll
        for (int i = 0; i < 8; i++) xq[i] = xsq[ty * 8 + i];

        #pragma unroll
        for (int j = 0; j < 8; j++) {
            int   codeIdx = cbase + tx * 8 + j;
            float cs      = csq[tx * 8 + j];
            #pragma unroll
            for (int p = 0; p < 4; p++) {
                unsigned long long a = acc[p][j];
                float dot0 = __uint_as_float((unsigned)(a & 0xffffffffULL));
                float dot1 = __uint_as_float((unsigned)(a >> 32));
                float d0 = (xq[2 * p]     - 2.0f * dot0) + cs;
                float d1 = (xq[2 * p + 1] - 2.0f * dot1) + cs;
                if (d0 < rv[2 * p])     { rv[2 * p]     = d0; ri[2 * p]     = codeIdx; }
                if (d1 < rv[2 * p + 1]) { rv[2 * p + 1] = d1; ri[2 * p + 1] = codeIdx; }
            }
        }
    }

    // ---- cross-thread argmin reduce (16 code-threads per row) ----
    __syncthreads();   // done with Bs2 before aliasing
    #pragma unroll
    for (int i = 0; i < 8; i++) {
        int row = ty * 8 + i;
        redval[row * 16 + tx] = rv[i];
        redidx[row * 16 + tx] = ri[i];
    }
    __syncthreads();
    if (tid < 128) {
        float bv = redval[tid * 16];
        int   bi = redidx[tid * 16];
        #pragma unroll
        for (int t = 1; t < 16; t++) {
            float v  = redval[tid * 16 + t];
            int   ix = redidx[tid * 16 + t];
            if (v < bv || (v == bv && ix < bi)) { bv = v; bi = ix; }
        }
        zsh[tid] = bi;
        out[rowBase + tid] = (float)bi;   // Z as float
    }
    __syncthreads();

    // ---- epilogue: q_with_st = x + (q - x); loss accum ----
    double lsum = 0.0;
    const size_t qbase = (size_t)N;
    #pragma unroll
    for (int t = 0; t < (BM * DDIM) / NTHREADS; t++) {
        int lin = tid + t * NTHREADS;
        int row = lin >> 6;
        int d   = lin & 63;
        int z   = zsh[row];
        float xv = x[(size_t)(rowBase + row) * DDIM + d];
        float qv = cb[(size_t)z * DDIM + d];
        float diff = qv - xv;
        out[qbase + (size_t)(rowBase + row) * DDIM + d] = xv + diff;
        lsum += (double)diff * (double)diff;
    }
    dred[tid] = lsum;
    __syncthreads();
    #pragma unroll
    for (int s = 128; s > 0; s >>= 1) {
        if (tid < s) dred[tid] += dred[tid + s];
        __syncthreads();
    }
    if (tid == 0) atomicAdd(&g_loss_accum, dred[0]);
}

// ---------------------------------------------------------------------------
extern "C" void kernel_launch(void* const* d_in, const int* in_sizes, int n_in,
                              void* d_out, int out_size) {
    const float* x  = (const float*)d_in[0];
    const float* cb = (const float*)d_in[1];
    float* out = (float*)d_out;

    int N = in_sizes[0] / DDIM;   // 262144
    int K = in_sizes[1] / DDIM;   // 1024

    size_t smemBytes = SMEM_FLOATS * sizeof(float);
    cudaFuncSetAttribute(vq_main_kernel,
                         cudaFuncAttributeMaxDynamicSharedMemorySize,
                         (int)smemBytes);

    zero_kernel<<<1, 1>>>();
    csq_kernel<<<(K + 127) / 128, 128>>>(cb, K);
    vq_main_kernel<<<N / BM, NTHREADS, smemBytes>>>(x, cb, out, N, K);
    finalize_kernel<<<1, 1>>>(out, N);
}

// round 2
// speedup vs baseline: 3.6229x; 3.6229x over previous
#include <cuda_runtime.h>
#include <cstdint>

// VQ-VAE codebook quantization, fused fp32 GEMM + argmin + gather + loss.
// N=262144 rows (x), K=1024 codes, D=64.
// Output layout (fp32): [0,N): Z (as float), [N, N+N*D): q_with_st, then 2 losses.
//
// R2: FMA2-bound SGEMM-style tiling. Block tile 256 rows x 128 codes, 256 threads,
// per-thread 16 rows x 8 codes held as 8 row-pair f32x2 accumulators x 8 codes.
// B tile stored row-major with pad-65 -> conflict-free scalar reads.

#define DDIM 64
#define BM 256       // rows per block
#define BK 128       // codes per chunk
#define NT 256

__device__ double g_loss_accum;
__device__ float  g_csq[4096];

// ---------------------------------------------------------------------------
__global__ void csq_kernel(const float* __restrict__ cb, int K) {
    int k = blockIdx.x * blockDim.x + threadIdx.x;
    if (k < K) {
        float s = 0.f;
        #pragma unroll
        for (int d = 0; d < DDIM; d++) {
            float v = cb[(size_t)k * DDIM + d];
            s += v * v;
        }
        g_csq[k] = s;
    }
}

__global__ void zero_kernel() { g_loss_accum = 0.0; }

__global__ void finalize_kernel(float* __restrict__ out, int N) {
    double mean = g_loss_accum / ((double)N * (double)DDIM);
    size_t base = (size_t)N + (size_t)N * DDIM;
    out[base]     = (float)mean;  // vq_loss
    out[base + 1] = (float)mean;  // commitment_loss (numerically identical)
}

// ---------------------------------------------------------------------------
__device__ __forceinline__ unsigned long long fma2(unsigned long long a,
                                                   unsigned long long b,
                                                   unsigned long long c) {
    unsigned long long d;
    asm("fma.rn.f32x2 %0, %1, %2, %3;" : "=l"(d) : "l"(a), "l"(b), "l"(c));
    return d;
}
__device__ __forceinline__ unsigned long long splat2(float v) {
    unsigned long long r;
    asm("mov.b64 %0, {%1, %1};" : "=l"(r) : "f"(v));
    return r;
}
__device__ __forceinline__ unsigned long long pack2(float a, float b) {
    unsigned long long r;
    asm("mov.b64 %0, {%1, %2};" : "=l"(r) : "f"(a), "f"(b));
    return r;
}
__device__ __forceinline__ float2 unpack2(unsigned long long v) {
    float2 f;
    asm("mov.b64 {%0, %1}, %2;" : "=f"(f.x), "=f"(f.y) : "l"(v));
    return f;
}

// Shared memory layout (floats):
//   As   [64][256]   x tile transposed (d-major)      16384
//   Bs   [128][65]   code chunk row-major, pad 65      8320
//   xsq  [256]
//   csq  [128]
//   rvs  [256][16]   running min value per (row, tx)   4096
//   ris  [256][16]   running min index                 4096 (int)
//   zsh  [256]       final argmin per row              (int)
//   dred [256]       double reduce                     512 float-slots
#define OFF_AS   0
#define OFF_BS   (64*256)
#define OFF_XSQ  (OFF_BS + 128*65)
#define OFF_CSQ  (OFF_XSQ + 256)
#define OFF_RVS  (OFF_CSQ + 128)
#define OFF_RIS  (OFF_RVS + 4096)
#define OFF_ZSH  (OFF_RIS + 4096)
#define OFF_DRED (OFF_ZSH + 256)
#define SMEM_FLOATS (OFF_DRED + 512)

__global__ __launch_bounds__(NT, 1)
void vq_main_kernel(const float* __restrict__ x, const float* __restrict__ cb,
                    float* __restrict__ out, int N, int K) {
    extern __shared__ float smem[];
    float*  As    = smem + OFF_AS;
    float*  Bs    = smem + OFF_BS;
    float*  xsq_s = smem + OFF_XSQ;
    float*  csq_s = smem + OFF_CSQ;
    float*  rvs   = smem + OFF_RVS;
    int*    ris   = (int*)(smem + OFF_RIS);
    int*    zsh   = (int*)(smem + OFF_ZSH);
    double* dred  = (double*)(smem + OFF_DRED);

    const int tid = threadIdx.x;
    const int tx  = tid & 15;    // code lane 0..15 (codes tx + 16*j)
    const int ty  = tid >> 4;    // row group 0..15 (rows ty*16 .. ty*16+15)
    const int rowBase = blockIdx.x * BM;

    // ---- load x tile transposed: As[d][row] (one-time; store conflicts OK) ----
    #pragma unroll
    for (int t = 0; t < (BM * DDIM) / (NT * 4); t++) {   // 16 iters of float4
        int lin = tid + t * NT;            // 0..4095
        int row = lin >> 4;
        int dg  = (lin & 15) << 2;
        float4 v = *(const float4*)(x + (size_t)(rowBase + row) * DDIM + dg);
        As[(dg + 0) * BM + row] = v.x;
        As[(dg + 1) * BM + row] = v.y;
        As[(dg + 2) * BM + row] = v.z;
        As[(dg + 3) * BM + row] = v.w;
    }
    // init running-min arrays: 4096 entries, 16 per thread
    #pragma unroll
    for (int t = 0; t < 16; t++) {
        rvs[tid + t * NT] = 3.4e38f;
        ris[tid + t * NT] = 0;
    }
    __syncthreads();

    // ---- x_sq per row (sequential over d, same order as R1: exact match) ----
    {
        float s = 0.f;
        #pragma unroll
        for (int d = 0; d < DDIM; d++) {
            float v = As[d * BM + tid];
            s += v * v;
        }
        xsq_s[tid] = s;
    }

    #pragma unroll 1
    for (int cbase = 0; cbase < K; cbase += BK) {
        __syncthreads();   // previous chunk fully consumed before overwriting Bs

        // ---- load code chunk row-major padded: Bs[code*65 + d] ----
        #pragma unroll
        for (int t = 0; t < (BK * DDIM) / (NT * 4); t++) {   // 8 iters of float4
            int lin  = tid + t * NT;         // 0..2047
            int code = lin >> 4;             // 0..127
            int dg   = (lin & 15) << 2;      // 0..60
            float4 v = *(const float4*)(cb + (size_t)(cbase + code) * DDIM + dg);
            Bs[code * 65 + dg + 0] = v.x;
            Bs[code * 65 + dg + 1] = v.y;
            Bs[code * 65 + dg + 2] = v.z;
            Bs[code * 65 + dg + 3] = v.w;
        }
        if (tid < BK) csq_s[tid] = g_csq[cbase + tid];
        __syncthreads();

        // ---- mainloop: 16 rows (8 f32x2 pairs) x 8 codes per thread ----
        unsigned long long acc[8][8];
        #pragma unroll
        for (int p = 0; p < 8; p++)
            #pragma unroll
            for (int j = 0; j < 8; j++) acc[p][j] = 0ULL;

        const float* aBase = As + ty * 16;
        const float* bBase = Bs + tx * 65;

        #pragma unroll 8
        for (int d = 0; d < DDIM; d++) {
            const float4* arow = (const float4*)(aBase + d * BM);
            float4 a0 = arow[0], a1 = arow[1], a2 = arow[2], a3 = arow[3];
            unsigned long long ap[8];
            ap[0] = pack2(a0.x, a0.y); ap[1] = pack2(a0.z, a0.w);
            ap[2] = pack2(a1.x, a1.y); ap[3] = pack2(a1.z, a1.w);
            ap[4] = pack2(a2.x, a2.y); ap[5] = pack2(a2.z, a2.w);
            ap[6] = pack2(a3.x, a3.y); ap[7] = pack2(a3.z, a3.w);

            unsigned long long bp[8];
            #pragma unroll
            for (int j = 0; j < 8; j++)
                bp[j] = splat2(bBase[j * (16 * 65) + d]);

            #pragma unroll
            for (int p = 0; p < 8; p++)
                #pragma unroll
                for (int j = 0; j < 8; j++)
                    acc[p][j] = fma2(ap[p], bp[j], acc[p][j]);
        }

        // ---- distances + per-chunk argmin, merge into persistent smem ----
        float cs[8];
        #pragma unroll
        for (int j = 0; j < 8; j++) cs[j] = csq_s[tx + 16 * j];

        #pragma unroll
        for (int p = 0; p < 8; p++) {
            int r0 = ty * 16 + 2 * p;
            float xq0 = xsq_s[r0];
            float xq1 = xsq_s[r0 + 1];
            float bv0 = 3.4e38f, bv1 = 3.4e38f;
            int   bi0 = 0,       bi1 = 0;
            #pragma unroll
            for (int j = 0; j < 8; j++) {
                float2 dd = unpack2(acc[p][j]);
                float d0 = (xq0 - 2.0f * dd.x) + cs[j];
                float d1 = (xq1 - 2.0f * dd.y) + cs[j];
                int code = cbase + tx + 16 * j;      // ascending in j
                if (d0 < bv0) { bv0 = d0; bi0 = code; }
                if (d1 < bv1) { bv1 = d1; bi1 = code; }
            }
            int s0 = r0 * 16 + tx;
            int s1 = s0 + 16;
            if (bv0 < rvs[s0]) { rvs[s0] = bv0; ris[s0] = bi0; }
            if (bv1 < rvs[s1]) { rvs[s1] = bv1; ris[s1] = bi1; }
        }
    }

    // ---- cross-tx argmin reduce: thread tid owns row tid ----
    __syncthreads();
    {
        float bv = rvs[tid * 16];
        int   bi = ris[tid * 16];
        #pragma unroll
        for (int t = 1; t < 16; t++) {
            float v  = rvs[tid * 16 + t];
            int   ix = ris[tid * 16 + t];
            if (v < bv || (v == bv && ix < bi)) { bv = v; bi = ix; }
        }
        zsh[tid] = bi;
        out[rowBase + tid] = (float)bi;   // Z as float
    }
    __syncthreads();

    // ---- epilogue: q_with_st = x + (q - x); loss accum in double ----
    double lsum = 0.0;
    const size_t qbase = (size_t)N;
    #pragma unroll
    for (int t = 0; t < (BM * DDIM) / (NT * 4); t++) {   // 16 iters of float4
        int lin4 = tid + t * NT;           // 0..4095
        int row  = lin4 >> 4;
        int dq   = (lin4 & 15) << 2;
        int z    = zsh[row];
        float4 xv = *(const float4*)(x  + (size_t)(rowBase + row) * DDIM + dq);
        float4 qv = *(const float4*)(cb + (size_t)z * DDIM + dq);
        float dx = qv.x - xv.x, dy = qv.y - xv.y, dz = qv.z - xv.z, dw = qv.w - xv.w;
        float4 o = make_float4(xv.x + dx, xv.y + dy, xv.z + dz, xv.w + dw);
        *(float4*)(out + qbase + (size_t)(rowBase + row) * DDIM + dq) = o;
        lsum += (double)dx * dx + (double)dy * dy + (double)dz * dz + (double)dw * dw;
    }
    dred[tid] = lsum;
    __syncthreads();
    #pragma unroll
    for (int s = 128; s > 0; s >>= 1) {
        if (tid < s) dred[tid] += dred[tid + s];
        __syncthreads();
    }
    if (tid == 0) atomicAdd(&g_loss_accum, dred[0]);
}

// ---------------------------------------------------------------------------
extern "C" void kernel_launch(void* const* d_in, const int* in_sizes, int n_in,
                              void* d_out, int out_size) {
    const float* x  = (const float*)d_in[0];
    const float* cb = (const float*)d_in[1];
    float* out = (float*)d_out;

    int N = in_sizes[0] / DDIM;   // 262144
    int K = in_sizes[1] / DDIM;   // 1024

    size_t smemBytes = SMEM_FLOATS * sizeof(float);
    cudaFuncSetAttribute(vq_main_kernel,
                         cudaFuncAttributeMaxDynamicSharedMemorySize,
                         (int)smemBytes);

    zero_kernel<<<1, 1>>>();
    csq_kernel<<<(K + 127) / 128, 128>>>(cb, K);
    vq_main_kernel<<<N / BM, NT, smemBytes>>>(x, cb, out, N, K);
    finalize_kernel<<<1, 1>>>(out, N);
}